// round 2
// baseline (speedup 1.0000x reference)
#include <cuda_runtime.h>

// ---------------------------------------------------------------------------
// CausalEdgeAttention — algebraically reduced.
//   out = edge_attr + 0.5*((relu(ctx@W1+b1) * g) @ M + const8)
//   ctx = 0.5*(nf[src]+nf[tgt]);  M = n_W2@Wv@Wo@Wp (256x8)
//   g/shift from BatchNorm batch stats of h=relu(ctx@W1+b1) over all E edges.
//   edge encoder branch of the reference is dead code (never used in output).
// ---------------------------------------------------------------------------

#define NBLK_STATS 296   // 2 blocks per SM (148 SMs)

__device__ float g_U[256 * 8];
__device__ float g_V[256 * 8];
__device__ float g_M[256 * 8];
__device__ float g_Mg[256 * 8];
__device__ float g_c1[256];
__device__ float g_c2[256];
__device__ float g_c3[8];
__device__ float g_const8[8];
__device__ float g_part[NBLK_STATS * 512];   // per-block partial sum/sumsq

// ---- tiny weight-folding kernels -----------------------------------------
// U = Wo@Wp ; c1 = n_b2@Wv + bv
__global__ void kA(const float* __restrict__ Wo, const float* __restrict__ Wp,
                   const float* __restrict__ nb2, const float* __restrict__ Wv,
                   const float* __restrict__ bv) {
    int tid = blockIdx.x * blockDim.x + threadIdx.x;
    if (tid < 2048) {
        int i = tid >> 3, d = tid & 7;
        float acc = 0.f;
        for (int k = 0; k < 256; k++) acc += Wo[i * 256 + k] * Wp[k * 8 + d];
        g_U[tid] = acc;
    } else if (tid < 2304) {
        int i = tid - 2048;
        float acc = bv[i];
        for (int k = 0; k < 256; k++) acc += nb2[k] * Wv[k * 256 + i];
        g_c1[i] = acc;
    }
}

// V = Wv@U ; c2 = c1@Wo + bo
__global__ void kB(const float* __restrict__ Wv, const float* __restrict__ Wo,
                   const float* __restrict__ bo) {
    int tid = blockIdx.x * blockDim.x + threadIdx.x;
    if (tid < 2048) {
        int i = tid >> 3, d = tid & 7;
        float acc = 0.f;
        for (int k = 0; k < 256; k++) acc += Wv[i * 256 + k] * g_U[k * 8 + d];
        g_V[tid] = acc;
    } else if (tid < 2304) {
        int i = tid - 2048;
        float acc = bo[i];
        for (int k = 0; k < 256; k++) acc += g_c1[k] * Wo[k * 256 + i];
        g_c2[i] = acc;
    }
}

// M = n_W2@V ; c3 = c2@Wp + bp
__global__ void kC(const float* __restrict__ nW2, const float* __restrict__ Wp,
                   const float* __restrict__ bp) {
    int tid = blockIdx.x * blockDim.x + threadIdx.x;
    if (tid < 2048) {
        int i = tid >> 3, d = tid & 7;
        float acc = 0.f;
        for (int k = 0; k < 256; k++) acc += nW2[i * 256 + k] * g_V[k * 8 + d];
        g_M[tid] = acc;
    } else if (tid < 2056) {
        int d = tid - 2048;
        float acc = bp[d];
        for (int k = 0; k < 256; k++) acc += g_c2[k] * Wp[k * 8 + d];
        g_c3[d] = acc;
    }
}

// ---- pass 1: batch stats of h = relu(ctx@W1+b1), warp-per-edge -----------
__global__ void __launch_bounds__(256) kStats(
    const float* __restrict__ nf, const int* __restrict__ ei,
    const float* __restrict__ W1, const float* __restrict__ b1, int E) {
    __shared__ float psum[8][256];
    __shared__ float psq[8][256];

    int tid = threadIdx.x;
    int lane = tid & 31;
    int warpInBlock = tid >> 5;
    int warpGlobal = (blockIdx.x * blockDim.x + tid) >> 5;
    int nWarps = (gridDim.x * blockDim.x) >> 5;

    // lane owns columns j = 32k+lane, k=0..7 ; weights live in registers
    float w[8][8], bb[8];
#pragma unroll
    for (int k = 0; k < 8; k++) {
        int j = k * 32 + lane;
        bb[k] = b1[j];
#pragma unroll
        for (int d = 0; d < 8; d++) w[k][d] = W1[d * 256 + j];
    }

    float s[8], q[8];
#pragma unroll
    for (int k = 0; k < 8; k++) { s[k] = 0.f; q[k] = 0.f; }

    const float4* nf4 = (const float4*)nf;
    for (int e = warpGlobal; e < E; e += nWarps) {
        int a = ei[e], b = ei[E + e];
        float4 a0 = nf4[a * 2], a1 = nf4[a * 2 + 1];
        float4 b0 = nf4[b * 2], b1v = nf4[b * 2 + 1];
        float c0 = 0.5f * (a0.x + b0.x), c1_ = 0.5f * (a0.y + b0.y);
        float c2_ = 0.5f * (a0.z + b0.z), c3_ = 0.5f * (a0.w + b0.w);
        float c4 = 0.5f * (a1.x + b1v.x), c5 = 0.5f * (a1.y + b1v.y);
        float c6 = 0.5f * (a1.z + b1v.z), c7 = 0.5f * (a1.w + b1v.w);
#pragma unroll
        for (int k = 0; k < 8; k++) {
            float h = bb[k];
            h += c0 * w[k][0]; h += c1_ * w[k][1];
            h += c2_ * w[k][2]; h += c3_ * w[k][3];
            h += c4 * w[k][4]; h += c5 * w[k][5];
            h += c6 * w[k][6]; h += c7 * w[k][7];
            h = fmaxf(h, 0.f);
            s[k] += h;
            q[k] += h * h;
        }
    }

#pragma unroll
    for (int k = 0; k < 8; k++) {
        psum[warpInBlock][k * 32 + lane] = s[k];
        psq[warpInBlock][k * 32 + lane] = q[k];
    }
    __syncthreads();

    float ts = 0.f, tq = 0.f;
#pragma unroll
    for (int wb = 0; wb < 8; wb++) { ts += psum[wb][tid]; tq += psq[wb][tid]; }
    g_part[blockIdx.x * 512 + tid] = ts;
    g_part[blockIdx.x * 512 + 256 + tid] = tq;
}

// ---- finalize: fold BN into Mg and const8 --------------------------------
__global__ void kFin(const float* __restrict__ gamma,
                     const float* __restrict__ beta, float invE) {
    __shared__ float sh[256];
    int j = threadIdx.x;

    float s = 0.f, q = 0.f;
    for (int b = 0; b < NBLK_STATS; b++) {
        s += g_part[b * 512 + j];
        q += g_part[b * 512 + 256 + j];
    }
    float mu = s * invE;
    float var = q * invE - mu * mu;
    float gg = gamma[j] * rsqrtf(var + 1e-5f);
    float shift = beta[j] - mu * gg;
    sh[j] = shift;
#pragma unroll
    for (int d = 0; d < 8; d++) g_Mg[j * 8 + d] = gg * g_M[j * 8 + d];
    __syncthreads();

    int w = j >> 5, lane = j & 31;  // warp w -> const8[w]
    float acc = 0.f;
    for (int jj = lane; jj < 256; jj += 32) acc += sh[jj] * g_M[jj * 8 + w];
#pragma unroll
    for (int off = 16; off; off >>= 1)
        acc += __shfl_xor_sync(0xffffffffu, acc, off);
    if (lane == 0) g_const8[w] = acc + g_c3[w];
}

// ---- pass 2: output, thread-per-edge -------------------------------------
__global__ void __launch_bounds__(256) kOut(
    const float* __restrict__ nf, const int* __restrict__ ei,
    const float* __restrict__ W1, const float* __restrict__ b1,
    const float* __restrict__ ea, float* __restrict__ out, int E) {
    __shared__ float4 sW[512];  // W1 transposed: row j = 8 floats
    __shared__ float4 sM[512];  // g-scaled M: row j = 8 floats
    __shared__ float sB[256];
    __shared__ float sC[8];

    int tid = threadIdx.x;
    float* sWf = (float*)sW;
    float* sMf = (float*)sM;
    for (int i = tid; i < 2048; i += 256) {
        int j = i >> 3, d = i & 7;
        sWf[i] = W1[d * 256 + j];
        sMf[i] = g_Mg[i];
    }
    sB[tid] = b1[tid];
    if (tid < 8) sC[tid] = g_const8[tid];
    __syncthreads();

    int e = blockIdx.x * 256 + tid;
    if (e >= E) return;

    int a = ei[e], b = ei[E + e];
    const float4* nf4 = (const float4*)nf;
    float4 a0 = nf4[a * 2], a1 = nf4[a * 2 + 1];
    float4 b0 = nf4[b * 2], b1v = nf4[b * 2 + 1];
    float c[8];
    c[0] = 0.5f * (a0.x + b0.x); c[1] = 0.5f * (a0.y + b0.y);
    c[2] = 0.5f * (a0.z + b0.z); c[3] = 0.5f * (a0.w + b0.w);
    c[4] = 0.5f * (a1.x + b1v.x); c[5] = 0.5f * (a1.y + b1v.y);
    c[6] = 0.5f * (a1.z + b1v.z); c[7] = 0.5f * (a1.w + b1v.w);

    float y[8];
#pragma unroll
    for (int d = 0; d < 8; d++) y[d] = 0.f;

#pragma unroll 8
    for (int j = 0; j < 256; j++) {
        float4 w0 = sW[j * 2], w1 = sW[j * 2 + 1];
        float h = sB[j];
        h += c[0] * w0.x; h += c[1] * w0.y; h += c[2] * w0.z; h += c[3] * w0.w;
        h += c[4] * w1.x; h += c[5] * w1.y; h += c[6] * w1.z; h += c[7] * w1.w;
        h = fmaxf(h, 0.f);
        float4 m0 = sM[j * 2], m1 = sM[j * 2 + 1];
        y[0] += h * m0.x; y[1] += h * m0.y; y[2] += h * m0.z; y[3] += h * m0.w;
        y[4] += h * m1.x; y[5] += h * m1.y; y[6] += h * m1.z; y[7] += h * m1.w;
    }

    const float4* ea4 = (const float4*)ea;
    float4 e0 = ea4[e * 2], e1 = ea4[e * 2 + 1];
    float4 o0, o1;
    o0.x = e0.x + 0.5f * (y[0] + sC[0]);
    o0.y = e0.y + 0.5f * (y[1] + sC[1]);
    o0.z = e0.z + 0.5f * (y[2] + sC[2]);
    o0.w = e0.w + 0.5f * (y[3] + sC[3]);
    o1.x = e1.x + 0.5f * (y[4] + sC[4]);
    o1.y = e1.y + 0.5f * (y[5] + sC[5]);
    o1.z = e1.z + 0.5f * (y[6] + sC[6]);
    o1.w = e1.w + 0.5f * (y[7] + sC[7]);
    float4* out4 = (float4*)out;
    out4[e * 2] = o0;
    out4[e * 2 + 1] = o1;
}

// ---------------------------------------------------------------------------
extern "C" void kernel_launch(void* const* d_in, const int* in_sizes, int n_in,
                              void* d_out, int out_size) {
    const float* edge_attr = (const float*)d_in[0];
    const float* nf        = (const float*)d_in[1];
    const int*   ei        = (const int*)d_in[2];
    // d_in[3..8]: edge-encoder params (dead code in reference)
    const float* nW1   = (const float*)d_in[9];
    const float* nb1   = (const float*)d_in[10];
    const float* ngam  = (const float*)d_in[11];
    const float* nbet  = (const float*)d_in[12];
    const float* nW2   = (const float*)d_in[13];
    const float* nb2   = (const float*)d_in[14];
    const float* Wv    = (const float*)d_in[15];
    const float* bv    = (const float*)d_in[16];
    const float* Wo    = (const float*)d_in[17];
    const float* bo    = (const float*)d_in[18];
    const float* Wp    = (const float*)d_in[19];
    const float* bp    = (const float*)d_in[20];
    float* out = (float*)d_out;

    int E = in_sizes[0] / 8;

    kA<<<9, 256>>>(Wo, Wp, nb2, Wv, bv);
    kB<<<9, 256>>>(Wv, Wo, bo);
    kC<<<9, 256>>>(nW2, Wp, bp);
    kStats<<<NBLK_STATS, 256>>>(nf, ei, nW1, nb1, E);
    kFin<<<1, 256>>>(ngam, nbet, 1.0f / (float)E);
    kOut<<<(E + 255) / 256, 256>>>(nf, ei, nW1, nb1, edge_attr, out, E);
}